// round 2
// baseline (speedup 1.0000x reference)
#include <cuda_runtime.h>
#include <stdint.h>

#define NUM_NODES 50000
#define NUM_EDGES 600000
#define DD 128
#define FF 128

// Scratch: aggregated messages [NUM_NODES, D]
__device__ float g_agg[NUM_NODES * DD];
// Flag: 1 if index arrays are int64, 0 if int32
__device__ int g_is64;

// ---------------------------------------------------------------------------
// Detect index dtype. int64 data with values < 50000 has zero high words at
// every odd 32-bit position; int32 data has (almost always) nonzero values
// there. Deterministic given the input buffer.
// ---------------------------------------------------------------------------
__global__ void detect_kernel(const int* __restrict__ w) {
    __shared__ int cnt;
    if (threadIdx.x == 0) cnt = 0;
    __syncthreads();
    int nz = 0;
    // examine first 1024 odd words (within 8KB, safe for either dtype)
    for (int i = threadIdx.x * 2 + 1; i < 2048; i += 2 * blockDim.x)
        nz += (w[i] != 0);
    atomicAdd(&cnt, nz);
    __syncthreads();
    if (threadIdx.x == 0) g_is64 = (cnt < 512) ? 1 : 0;
}

// ---------------------------------------------------------------------------
// Zero the aggregation buffer (float4 stores, fully coalesced)
// ---------------------------------------------------------------------------
__global__ void zero_kernel() {
    int i = blockIdx.x * blockDim.x + threadIdx.x;
    float4 z = make_float4(0.f, 0.f, 0.f, 0.f);
    if (i < NUM_NODES * DD / 4) reinterpret_cast<float4*>(g_agg)[i] = z;
}

// ---------------------------------------------------------------------------
// Scatter-add: one warp per edge. Lane l moves float4 #l of the 128-float row.
// 512B coalesced gather from node_x, 16B vector reduction into g_agg.
// ---------------------------------------------------------------------------
__global__ void scatter_kernel(const float* __restrict__ x,
                               const void* __restrict__ src,
                               const void* __restrict__ tgt) {
    int e = (blockIdx.x * blockDim.x + threadIdx.x) >> 5;
    if (e >= NUM_EDGES) return;
    int lane = threadIdx.x & 31;

    long long s, t;
    if (g_is64) {
        s = reinterpret_cast<const long long*>(src)[e];
        t = reinterpret_cast<const long long*>(tgt)[e];
    } else {
        s = reinterpret_cast<const int*>(src)[e];
        t = reinterpret_cast<const int*>(tgt)[e];
    }

    float4 v = reinterpret_cast<const float4*>(x + s * DD)[lane];
    float* dst = g_agg + t * DD + lane * 4;
    asm volatile("red.global.add.v4.f32 [%0], {%1, %2, %3, %4};"
                 :: "l"(dst), "f"(v.x), "f"(v.y), "f"(v.z), "f"(v.w)
                 : "memory");
}

// ---------------------------------------------------------------------------
// GEMM: out[n, j] = sum_k H[n,k] * W[k,j] + b[j],  H = [agg | x]  (K = 256)
// Block: 64 nodes x 128 features, 256 threads.
// Smem: full W (256x128 = 128KB) + H tile (64x256 = 64KB) = 192KB dynamic.
// Thread (t): features j4 = 4*(t%32), nodes  ng*8..ng*8+7 with ng = t/32.
// Warp = one node-group -> all H smem loads are broadcasts; W loads are
// 32 consecutive float4s -> conflict-free. LDS:FFMA ~ 1:10 -> FFMA-bound.
// ---------------------------------------------------------------------------
__global__ void __launch_bounds__(256, 1)
gemm_kernel(const float* __restrict__ x, const float* __restrict__ W,
            const float* __restrict__ b, float* __restrict__ out) {
    extern __shared__ float smem[];
    float* Ws = smem;              // [256][128]
    float* Hs = smem + 256 * 128;  // [64][256]

    int tid = threadIdx.x;
    int nbase = blockIdx.x * 64;

    // Load W (row-major, as-is)
    const float4* W4 = reinterpret_cast<const float4*>(W);
    float4* Ws4 = reinterpret_cast<float4*>(Ws);
    #pragma unroll
    for (int i = tid; i < 256 * 128 / 4; i += 256) Ws4[i] = W4[i];

    // Load H tile: row = [agg_row (32 float4) | x_row (32 float4)]
    for (int p = tid; p < 64 * 64; p += 256) {
        int n = p >> 6, c = p & 63;
        int node = nbase + n;
        float4 v = make_float4(0.f, 0.f, 0.f, 0.f);
        if (node < NUM_NODES) {
            if (c < 32) v = reinterpret_cast<const float4*>(g_agg + node * DD)[c];
            else        v = reinterpret_cast<const float4*>(x + node * DD)[c - 32];
        }
        reinterpret_cast<float4*>(Hs + n * 256)[c] = v;
    }
    __syncthreads();

    int j4 = (tid & 31) * 4;   // feature quad
    int ng = tid >> 5;         // node group (0..7)

    float acc[8][4];
    #pragma unroll
    for (int n = 0; n < 8; n++)
        #pragma unroll
        for (int f = 0; f < 4; f++) acc[n][f] = 0.f;

    #pragma unroll 4
    for (int k0 = 0; k0 < 256; k0 += 4) {
        float4 wv[4];
        #pragma unroll
        for (int kk = 0; kk < 4; kk++)
            wv[kk] = reinterpret_cast<const float4*>(Ws + (k0 + kk) * 128 + j4)[0];
        #pragma unroll
        for (int n = 0; n < 8; n++) {
            float4 hv = reinterpret_cast<const float4*>(Hs + (ng * 8 + n) * 256 + k0)[0];
            acc[n][0] += hv.x * wv[0].x + hv.y * wv[1].x + hv.z * wv[2].x + hv.w * wv[3].x;
            acc[n][1] += hv.x * wv[0].y + hv.y * wv[1].y + hv.z * wv[2].y + hv.w * wv[3].y;
            acc[n][2] += hv.x * wv[0].z + hv.y * wv[1].z + hv.z * wv[2].z + hv.w * wv[3].z;
            acc[n][3] += hv.x * wv[0].w + hv.y * wv[1].w + hv.z * wv[2].w + hv.w * wv[3].w;
        }
    }

    float4 bv = reinterpret_cast<const float4*>(b)[j4 >> 2];
    #pragma unroll
    for (int n = 0; n < 8; n++) {
        int node = nbase + ng * 8 + n;
        if (node < NUM_NODES) {
            float4 o = make_float4(acc[n][0] + bv.x, acc[n][1] + bv.y,
                                   acc[n][2] + bv.z, acc[n][3] + bv.w);
            reinterpret_cast<float4*>(out + node * FF)[j4 >> 2] = o;
        }
    }
}

extern "C" void kernel_launch(void* const* d_in, const int* in_sizes, int n_in,
                              void* d_out, int out_size) {
    const float* node_x = (const float*)d_in[0];
    const void*  sources = d_in[1];
    const void*  targets = d_in[2];
    const float* W = (const float*)d_in[3];
    const float* b = (const float*)d_in[4];
    float* out = (float*)d_out;

    cudaFuncSetAttribute(gemm_kernel,
                         cudaFuncAttributeMaxDynamicSharedMemorySize, 196608);

    detect_kernel<<<1, 256>>>((const int*)sources);
    zero_kernel<<<(NUM_NODES * DD / 4 + 255) / 256, 256>>>();

    long long threads = (long long)NUM_EDGES * 32;
    int blocks = (int)((threads + 255) / 256);
    scatter_kernel<<<blocks, 256>>>(node_x, sources, targets);

    gemm_kernel<<<(NUM_NODES + 63) / 64, 256, 196608>>>(node_x, W, b, out);
}